// round 16
// baseline (speedup 1.0000x reference)
#include <cuda_runtime.h>
#include <stdint.h>
#include <math.h>

// ---------------------------------------------------------------------------
// EncoderLayer: B=32, S=512, D=1024, H=16, dk=64, F=4096
// Round 14: packed-fp32 (fma.rn.f32x2) GEMM engine with FIXED injective B
// swizzle (r13's off(n)=n+4*((n>>5)&1) double-mapped words 64..67; now
// off(n)=n+4*(n>>5), BSTR=140, disjoint groups [36g,36g+32)).
// Full fp32 pipeline. Attention (512 thr) + LN unchanged.
// ---------------------------------------------------------------------------

#define B_  32
#define S_  512
#define D_  1024
#define H_  16
#define DK_ 64
#define F_  4096
#define M_  (B_ * S_)          // 16384 rows

// -------------------- scratch (device globals; no allocs) ------------------
__device__ float g_q   [M_ * D_];
__device__ float g_k   [M_ * D_];
__device__ float g_v   [M_ * D_];
__device__ float g_ctx [M_ * D_];
__device__ float g_attn[M_ * D_];
__device__ float g_out1[M_ * D_];
__device__ float g_ffn [M_ * D_];
__device__ float g_h   [M_ * F_];

// ---------------------------------------------------------------------------
// Helpers
// ---------------------------------------------------------------------------
__device__ __forceinline__ float gelu_erf_f(float x) {
    return 0.5f * x * (1.0f + erff(x * 0.70710678118654752f));
}
__device__ __forceinline__ uint32_t smem_u32(const void* p) {
    uint32_t a;
    asm("{ .reg .u64 t; cvta.to.shared.u64 t, %1; cvt.u32.u64 %0, t; }"
        : "=r"(a) : "l"(p));
    return a;
}
__device__ __forceinline__ void cp16(uint32_t s, const void* g) {
    asm volatile("cp.async.cg.shared.global [%0], [%1], 16;" :: "r"(s), "l"(g));
}
__device__ __forceinline__ void cp_commit() {
    asm volatile("cp.async.commit_group;" ::: "memory");
}
template <int N>
__device__ __forceinline__ void cp_wait() {
    asm volatile("cp.async.wait_group %0;" :: "n"(N) : "memory");
}
// packed fp32x2 helpers
__device__ __forceinline__ unsigned long long pack2(float x) {
    unsigned long long r;
    asm("mov.b64 %0, {%1, %1};" : "=l"(r) : "f"(x));
    return r;
}
__device__ __forceinline__ void fma2(unsigned long long& d,
                                     unsigned long long a, unsigned long long b) {
    asm("fma.rn.f32x2 %0, %1, %2, %0;" : "+l"(d) : "l"(a), "l"(b));
}
__device__ __forceinline__ void unpack2(float& lo, float& hi, unsigned long long v) {
    asm("mov.b64 {%0, %1}, %2;" : "=f"(lo), "=f"(hi) : "l"(v));
}

// injective B word swizzle: group g=[32g,32g+32) -> [36g, 36g+32)
__device__ __forceinline__ int bswz(int n) { return n + 4 * (n >> 5); }

// ---------------------------------------------------------------------------
// f32x2 GEMM: C[M,N] = act(A[M,K] @ W[K,N] + bias[N]), full fp32.
// CTA 128x128, BK=16, 4-stage cp.async, 256 threads = 8 warps (4x2),
// thread microtile 8x8 (rows strided x4; n-pairs for LDS64 B loads).
// Smem: As[m][k] stride 20; Bs[k][bswz(n)] stride 140 (injective swizzle,
// conflict-free LDS64 fragments: banks {0,8,16,24,4,12,20,28}+c).
// ---------------------------------------------------------------------------
#define ASTR 20
#define BSTR 140
#define STG_FLT (128 * ASTR + 16 * BSTR)   // 4800 floats
#define GEMM_SMEM (4 * STG_FLT * 4)        // 76800 bytes

template <int ACT>
__global__ __launch_bounds__(256, 2) void f2_gemm(
    const float* __restrict__ A, const float* __restrict__ W,
    const float* __restrict__ bias, float* __restrict__ C,
    int N, int K)
{
    extern __shared__ float sm[];

    const int tid = threadIdx.x;
    const int bx = blockIdx.x, by = blockIdx.y;
    const int wid = tid >> 5, lane = tid & 31;
    const int warp_m = wid >> 1;              // 0..3
    const int warp_n = wid & 1;               // 0..1
    const int mg = lane >> 3;                 // 0..3
    const int ng = lane & 7;                  // 0..7
    const int wm = warp_m * 32;               // rows wm + mg + 4*i
    const int n0 = (warp_n * 8 + ng) * 8;     // cols n0..n0+7
    const int bofs = bswz(n0);                // swizzled word offset

    // cp.async producer mapping
    const int arr = tid >> 1, ak = (tid & 1) * 8;    // A: 128 rows x 16 k
    const int bkr = tid >> 4, bn = (tid & 15) * 8;   // B: 16 k x 128 n
    const int w1 = bswz(bn);                         // bn..bn+7 stay in-group
    const uint32_t base = smem_u32(sm);
    const uint32_t sA0 = base + (uint32_t)(arr * ASTR + ak) * 4u;
    const uint32_t sB1 = base + (uint32_t)(128 * ASTR + bkr * BSTR + w1) * 4u;

    const float* Ag = A + (size_t)(by * 128 + arr) * K + ak;
    const float* Bg = W + (size_t)bkr * N + bx * 128 + bn;

    auto issue = [&](int kt) {
        const uint32_t so = (uint32_t)(kt & 3) * (STG_FLT * 4u);
        cp16(sA0 + so,      Ag + kt * 16);
        cp16(sA0 + so + 16, Ag + kt * 16 + 4);
        cp16(sB1 + so,      Bg + (size_t)(kt * 16) * N);
        cp16(sB1 + so + 16, Bg + (size_t)(kt * 16) * N + 4);
        cp_commit();
    };

    unsigned long long acc[8][4];
    #pragma unroll
    for (int i = 0; i < 8; i++)
        #pragma unroll
        for (int j = 0; j < 4; j++) acc[i][j] = 0ull;

    const int nk = K >> 4;   // BK = 16

    issue(0); issue(1); issue(2);

    for (int kt = 0; kt < nk; ++kt) {
        if (kt + 2 < nk) cp_wait<2>(); else cp_wait<0>();
        __syncthreads();
        if (kt + 3 < nk) issue(kt + 3);

        const float* As = sm + (kt & 3) * STG_FLT;
        const float* Bs = As + 128 * ASTR;

        #pragma unroll
        for (int k = 0; k < 16; ++k) {
            unsigned long long a2[8], b2[4];
            #pragma unroll
            for (int i = 0; i < 8; i++)
                a2[i] = pack2(As[(wm + mg + 4 * i) * ASTR + k]);
            const float* brow = Bs + k * BSTR + bofs;
            #pragma unroll
            for (int j = 0; j < 4; j++)
                b2[j] = *(const unsigned long long*)(brow + 2 * j);
            #pragma unroll
            for (int i = 0; i < 8; i++)
                #pragma unroll
                for (int j = 0; j < 4; j++)
                    fma2(acc[i][j], a2[i], b2[j]);
        }
        // next iteration's wait+sync gates reuse of this stage's buffer
    }

    // ---- epilogue: bias (+ GELU) + store ----
    #pragma unroll
    for (int i = 0; i < 8; i++) {
        const int row = by * 128 + wm + mg + 4 * i;
        float* Crow = C + (size_t)row * N + bx * 128;
        #pragma unroll
        for (int j = 0; j < 4; j++) {
            const int col = n0 + 2 * j;
            const float2 bb = *(const float2*)&bias[bx * 128 + col];
            float lo, hi;
            unpack2(lo, hi, acc[i][j]);
            lo += bb.x; hi += bb.y;
            if (ACT == 1) { lo = gelu_erf_f(lo); hi = gelu_erf_f(hi); }
            float2 o; o.x = lo; o.y = hi;
            *(float2*)&Crow[col] = o;
        }
    }
}

// ---------------------------------------------------------------------------
// Fused attention: grid (S/64, H, B), 512 threads (16 warps). fp32.
// ---------------------------------------------------------------------------
#define SC_STRIDE 516
#define QK_STRIDE 68

__global__ __launch_bounds__(512) void attention_kernel(
    const float* __restrict__ Q, const float* __restrict__ K,
    const float* __restrict__ V, const int* __restrict__ mask,
    const float* __restrict__ adj, float* __restrict__ ctx)
{
    extern __shared__ float smem[];
    float* sc = smem;
    float* qs = sc + 64 * SC_STRIDE;
    float* kv = qs + 64 * QK_STRIDE;

    const int t  = threadIdx.x;
    const int qt = blockIdx.x, h = blockIdx.y, b = blockIdx.z;
    const int qbase = b * S_ + qt * 64;

    #pragma unroll
    for (int i = 0; i < 2; i++) {
        int lin = t + i * 512;
        int r = lin >> 4, c4 = (lin & 15) << 2;
        float4 qv = *(const float4*)&Q[(size_t)(qbase + r) * D_ + h * DK_ + c4];
        qv.x *= 0.125f; qv.y *= 0.125f; qv.z *= 0.125f; qv.w *= 0.125f;
        *(float4*)&qs[r * QK_STRIDE + c4] = qv;
    }

    const int qi  = t >> 3;
    const int kj0 = (t & 7) << 3;
    const int qg  = qt * 64 + qi;

    for (int kt = 0; kt < 8; ++kt) {
        __syncthreads();
        #pragma unroll
        for (int i = 0; i < 2; i++) {
            int lin = t + i * 512;
            int r = lin >> 4, c4 = (lin & 15) << 2;
            float4 kk = *(const float4*)&K[(size_t)(b * S_ + kt * 64 + r) * D_ + h * DK_ + c4];
            kv[(c4 + 0) * QK_STRIDE + r] = kk.x;
            kv[(c4 + 1) * QK_STRIDE + r] = kk.y;
            kv[(c4 + 2) * QK_STRIDE + r] = kk.z;
            kv[(c4 + 3) * QK_STRIDE + r] = kk.w;
        }
        __syncthreads();

        float acc[8];
        #pragma unroll
        for (int j = 0; j < 8; j++) acc[j] = 0.f;

        #pragma unroll
        for (int d = 0; d < 64; ++d) {
            float qv = qs[qi * QK_STRIDE + d];
            const float4* kr = (const float4*)&kv[d * QK_STRIDE + kj0];
            float4 k0 = kr[0], k1 = kr[1];
            acc[0] += qv * k0.x; acc[1] += qv * k0.y; acc[2] += qv * k0.z; acc[3] += qv * k0.w;
            acc[4] += qv * k1.x; acc[5] += qv * k1.y; acc[6] += qv * k1.z; acc[7] += qv * k1.w;
        }

        const float* adjr = &adj[((size_t)(b * S_ + qg)) * S_ + kt * 64 + kj0];
        const int*   mr   = &mask[b * S_ + kt * 64 + kj0];
        float*       scr  = &sc[qi * SC_STRIDE + kt * 64 + kj0];
        #pragma unroll
        for (int j = 0; j < 8; j++)
            scr[j] = acc[j] + (float)mr[j] * -1e9f + adjr[j];
    }
    __syncthreads();

    {
        const int warp = t >> 5, lane = t & 31;
        for (int row = warp; row < 64; row += 16) {
            float* r = &sc[row * SC_STRIDE];
            float mx = -3.0e38f;
            #pragma unroll
            for (int i = 0; i < 16; i++) mx = fmaxf(mx, r[lane + 32 * i]);
            #pragma unroll
            for (int o = 16; o; o >>= 1) mx = fmaxf(mx, __shfl_xor_sync(0xffffffffu, mx, o));
            float e[16], sum = 0.f;
            #pragma unroll
            for (int i = 0; i < 16; i++) { e[i] = __expf(r[lane + 32 * i] - mx); sum += e[i]; }
            #pragma unroll
            for (int o = 16; o; o >>= 1) sum += __shfl_xor_sync(0xffffffffu, sum, o);
            const float inv = 1.0f / sum;
            #pragma unroll
            for (int i = 0; i < 16; i++) r[lane + 32 * i] = e[i] * inv;
        }
    }

    const int dc0 = kj0;
    float acc[8];
    #pragma unroll
    for (int j = 0; j < 8; j++) acc[j] = 0.f;

    for (int kt = 0; kt < 8; ++kt) {
        __syncthreads();
        #pragma unroll
        for (int i = 0; i < 2; i++) {
            int lin = t + i * 512;
            int r = lin >> 4, c4 = (lin & 15) << 2;
            float4 vv = *(const float4*)&V[(size_t)(b * S_ + kt * 64 + r) * D_ + h * DK_ + c4];
            *(float4*)&kv[r * QK_STRIDE + c4] = vv;
        }
        __syncthreads();

        #pragma unroll
        for (int kk = 0; kk < 64; ++kk) {
            float p = sc[qi * SC_STRIDE + kt * 64 + kk];
            const float4* vr = (const float4*)&kv[kk * QK_STRIDE + dc0];
            float4 v0 = vr[0], v1 = vr[1];
            acc[0] += p * v0.x; acc[1] += p * v0.y; acc[2] += p * v0.z; acc[3] += p * v0.w;
            acc[4] += p * v1.x; acc[5] += p * v1.y; acc[6] += p * v1.z; acc[7] += p * v1.w;
        }
    }

    float* outp = &ctx[(size_t)(qbase + qi) * D_ + h * DK_ + dc0];
    *(float4*)&outp[0] = *(float4*)&acc[0];
    *(float4*)&outp[4] = *(float4*)&acc[4];
}

// ---------------------------------------------------------------------------
// Residual + LayerNorm
// ---------------------------------------------------------------------------
__device__ __forceinline__ float blockReduceSum(float val, float* shared) {
    const int lane = threadIdx.x & 31, wid = threadIdx.x >> 5;
    #pragma unroll
    for (int o = 16; o; o >>= 1) val += __shfl_xor_sync(0xffffffffu, val, o);
    __syncthreads();
    if (lane == 0) shared[wid] = val;
    __syncthreads();
    float r = shared[0];
    #pragma unroll
    for (int w = 1; w < 8; w++) r += shared[w];
    return r;
}

__global__ __launch_bounds__(256) void ln_residual_kernel(
    const float* __restrict__ A, const float* __restrict__ Bm,
    const float* __restrict__ gamma, const float* __restrict__ beta,
    float* __restrict__ out)
{
    __shared__ float red[8];
    const int row = blockIdx.x;
    const int tid = threadIdx.x;
    const size_t base = (size_t)row * D_;

    float v[4];
    float s = 0.f;
    #pragma unroll
    for (int i = 0; i < 4; i++) {
        int c = tid + 256 * i;
        v[i] = A[base + c] + Bm[base + c];
        s += v[i];
    }
    s = blockReduceSum(s, red);
    const float mean = s * (1.0f / (float)D_);

    float s2 = 0.f;
    #pragma unroll
    for (int i = 0; i < 4; i++) { float d = v[i] - mean; s2 += d * d; }
    s2 = blockReduceSum(s2, red);

    const float stdv = sqrtf(s2 * (1.0f / (float)(D_ - 1)));   // ddof=1
    const float inv  = 1.0f / (stdv + 1e-6f);                  // /(std+eps)

    #pragma unroll
    for (int i = 0; i < 4; i++) {
        int c = tid + 256 * i;
        out[base + c] = gamma[c] * (v[i] - mean) * inv + beta[c];
    }
}

// ---------------------------------------------------------------------------
// launch
// ---------------------------------------------------------------------------
extern "C" void kernel_launch(void* const* d_in, const int* in_sizes, int n_in,
                              void* d_out, int out_size)
{
    const float* x    = (const float*)d_in[0];
    const int*   mask = (const int*)  d_in[1];
    const float* adj  = (const float*)d_in[2];
    const float* Wq = (const float*)d_in[4];  const float* bq = (const float*)d_in[5];
    const float* Wk = (const float*)d_in[6];  const float* bk = (const float*)d_in[7];
    const float* Wv = (const float*)d_in[8];  const float* bv = (const float*)d_in[9];
    const float* Wo = (const float*)d_in[10]; const float* bo = (const float*)d_in[11];
    const float* W1 = (const float*)d_in[12]; const float* b1 = (const float*)d_in[13];
    const float* W2 = (const float*)d_in[14]; const float* b2 = (const float*)d_in[15];
    const float* gamma = (const float*)d_in[16];
    const float* beta  = (const float*)d_in[17];
    float* out = (float*)d_out;

    float *q, *k, *v, *ctx, *attn, *out1, *ffn, *hbuf;
    cudaGetSymbolAddress((void**)&q,    g_q);
    cudaGetSymbolAddress((void**)&k,    g_k);
    cudaGetSymbolAddress((void**)&v,    g_v);
    cudaGetSymbolAddress((void**)&ctx,  g_ctx);
    cudaGetSymbolAddress((void**)&attn, g_attn);
    cudaGetSymbolAddress((void**)&out1, g_out1);
    cudaGetSymbolAddress((void**)&ffn,  g_ffn);
    cudaGetSymbolAddress((void**)&hbuf, g_h);

    cudaFuncSetAttribute(f2_gemm<0>,
                         cudaFuncAttributeMaxDynamicSharedMemorySize, GEMM_SMEM);
    cudaFuncSetAttribute(f2_gemm<1>,
                         cudaFuncAttributeMaxDynamicSharedMemorySize, GEMM_SMEM);

    const int ATTN_SMEM = (64 * SC_STRIDE + 2 * 64 * QK_STRIDE) * (int)sizeof(float);
    cudaFuncSetAttribute(attention_kernel,
                         cudaFuncAttributeMaxDynamicSharedMemorySize, ATTN_SMEM);

    dim3 gD(D_ / 128, M_ / 128);   // (8, 128)
    dim3 gF(F_ / 128, M_ / 128);   // (32, 128)

    // QKV projections (full fp32, packed-FFMA engine)
    f2_gemm<0><<<gD, 256, GEMM_SMEM>>>(x, Wq, bq, q, D_, D_);
    f2_gemm<0><<<gD, 256, GEMM_SMEM>>>(x, Wk, bk, k, D_, D_);
    f2_gemm<0><<<gD, 256, GEMM_SMEM>>>(x, Wv, bv, v, D_, D_);

    // attention
    dim3 gA(S_ / 64, H_, B_);
    attention_kernel<<<gA, 512, ATTN_SMEM>>>(q, k, v, mask, adj, ctx);

    // output projection
    f2_gemm<0><<<gD, 256, GEMM_SMEM>>>(ctx, Wo, bo, attn, D_, D_);

    // LN1
    ln_residual_kernel<<<M_, 256>>>(x, attn, gamma, beta, out1);

    // FFN
    f2_gemm<1><<<gF, 256, GEMM_SMEM>>>(out1, W1, b1, hbuf, F_, D_);
    f2_gemm<0><<<gD, 256, GEMM_SMEM>>>(hbuf, W2, b2, ffn, D_, F_);

    // LN2
    ln_residual_kernel<<<M_, 256>>>(out1, ffn, gamma, beta, out);
}

// round 17
// speedup vs baseline: 1.7228x; 1.7228x over previous
#include <cuda_runtime.h>
#include <stdint.h>
#include <math.h>

// ---------------------------------------------------------------------------
// EncoderLayer: B=32, S=512, D=1024, H=16, dk=64, F=4096
// Round 17: r9 engine (best known: tf32 mma + rna-preround, 7274us) +
//  - attention split to 32-row q-tiles (92KB smem -> 2 CTAs/SM)
//  - batched weight-rounding preprocessing (7 -> 4 launches)
//  - cp.async tail-wait fix (wait_group 0 on final stages)
// Engine ledger on sm_103a (measured): FFMA 34 TF/s, f32x2 34 (cracked),
// fp16 mma 45, tf32 mma 60.6 (rate-bound) -> tf32 mma is the ceiling.
// ---------------------------------------------------------------------------

#define B_  32
#define S_  512
#define D_  1024
#define H_  16
#define DK_ 64
#define F_  4096
#define M_  (B_ * S_)          // 16384 rows

// -------------------- scratch (device globals; no allocs) ------------------
__device__ float g_q    [M_ * D_];
__device__ float g_k    [M_ * D_];
__device__ float g_v    [M_ * D_];
__device__ float g_ctx  [M_ * D_];   // rounded (feeds Wo GEMM)
__device__ float g_attn [M_ * D_];
__device__ float g_out1 [M_ * D_];
__device__ float g_out1r[M_ * D_];   // rounded (feeds FFN1)
__device__ float g_ffn  [M_ * D_];
__device__ float g_h    [M_ * F_];   // rounded (feeds FFN2)
__device__ float g_xr   [M_ * D_];   // rounded x
__device__ float g_wqr  [D_ * D_];
__device__ float g_wkr  [D_ * D_];
__device__ float g_wvr  [D_ * D_];
__device__ float g_wor  [D_ * D_];
__device__ float g_w1r  [D_ * F_];
__device__ float g_w2r  [F_ * D_];

// ---------------------------------------------------------------------------
// Helpers
// ---------------------------------------------------------------------------
__device__ __forceinline__ float gelu_erf_f(float x) {
    return 0.5f * x * (1.0f + erff(x * 0.70710678118654752f));
}
__device__ __forceinline__ float tf32r(float f) {   // rna-round to tf32
    uint32_t u;
    asm("cvt.rna.tf32.f32 %0, %1;" : "=r"(u) : "f"(f));
    return __uint_as_float(u);
}
__device__ __forceinline__ uint32_t smem_u32(const void* p) {
    uint32_t a;
    asm("{ .reg .u64 t; cvta.to.shared.u64 t, %1; cvt.u32.u64 %0, t; }"
        : "=r"(a) : "l"(p));
    return a;
}
__device__ __forceinline__ void cp16(uint32_t s, const void* g) {
    asm volatile("cp.async.cg.shared.global [%0], [%1], 16;" :: "r"(s), "l"(g));
}
__device__ __forceinline__ void cp_commit() {
    asm volatile("cp.async.commit_group;" ::: "memory");
}
template <int N>
__device__ __forceinline__ void cp_wait() {
    asm volatile("cp.async.wait_group %0;" :: "n"(N) : "memory");
}
__device__ __forceinline__ void mma_tf32(float c[4],
                                         uint32_t a0, uint32_t a1, uint32_t a2, uint32_t a3,
                                         uint32_t b0, uint32_t b1) {
    asm volatile(
        "mma.sync.aligned.m16n8k8.row.col.f32.tf32.tf32.f32 "
        "{%0,%1,%2,%3}, {%4,%5,%6,%7}, {%8,%9}, {%0,%1,%2,%3};\n"
        : "+f"(c[0]), "+f"(c[1]), "+f"(c[2]), "+f"(c[3])
        : "r"(a0), "r"(a1), "r"(a2), "r"(a3), "r"(b0), "r"(b1));
}

// ---------------------------------------------------------------------------
// Preprocess: Y = tf32_rna(X); single-array and 4-array-batched variants
// ---------------------------------------------------------------------------
__global__ void rnd_kernel(const float* __restrict__ X, float* __restrict__ Y,
                           int n4) {
    int i = blockIdx.x * blockDim.x + threadIdx.x;
    if (i < n4) {
        float4 v = ((const float4*)X)[i];
        v.x = tf32r(v.x); v.y = tf32r(v.y); v.z = tf32r(v.z); v.w = tf32r(v.w);
        ((float4*)Y)[i] = v;
    }
}

// batches the four DxD weights (each D*D/4 = 262144 float4s)
__global__ void rnd4_kernel(const float* __restrict__ A, const float* __restrict__ Bp,
                            const float* __restrict__ Cp, const float* __restrict__ Dp,
                            float* __restrict__ a, float* __restrict__ b,
                            float* __restrict__ c, float* __restrict__ d) {
    int i = blockIdx.x * blockDim.x + threadIdx.x;   // 0 .. 4*262144-1
    const int sel = i >> 18;
    const int j   = i & 262143;
    const float* src = (sel == 0) ? A : (sel == 1) ? Bp : (sel == 2) ? Cp : Dp;
    float*       dst = (sel == 0) ? a : (sel == 1) ? b  : (sel == 2) ? c  : d;
    float4 v = ((const float4*)src)[j];
    v.x = tf32r(v.x); v.y = tf32r(v.y); v.z = tf32r(v.z); v.w = tf32r(v.w);
    ((float4*)dst)[j] = v;
}

// ---------------------------------------------------------------------------
// tf32 GEMM (r9 engine + tail-wait fix): C = act(A[M,K] @ W[K,N] + bias)
// CTA 128x128, BK=16, 4-stage cp.async, 256 threads = 8 warps (2x4),
// warp tile 64x32. Operands pre-rounded to tf32 in GMEM.
// ---------------------------------------------------------------------------
#define ASTR 20
#define BSTR 136
#define STG_FLT (128 * ASTR + 16 * BSTR)   // 4736
#define GEMM_SMEM (4 * STG_FLT * 4)        // 75776 bytes

template <int ACT, int ROUND>
__global__ __launch_bounds__(256, 2) void tf32_gemm(
    const float* __restrict__ A, const float* __restrict__ W,
    const float* __restrict__ bias, float* __restrict__ C,
    int N, int K)
{
    extern __shared__ float sm[];

    const int tid = threadIdx.x;
    const int bx = blockIdx.x, by = blockIdx.y;
    const int wid = tid >> 5, lane = tid & 31;
    const int wm = (wid >> 2) * 64;
    const int wn = (wid & 3) * 32;
    const int g  = lane >> 2;
    const int q  = lane & 3;

    const int ar = tid >> 1, ak = (tid & 1) * 8;
    const int bk = tid >> 4, bn = (tid & 15) * 8;
    const float* Ag = A + (size_t)(by * 128 + ar) * K + ak;
    const float* Bg = W + (size_t)bk * N + bx * 128 + bn;

    uint32_t sA0 = smem_u32(sm) + (uint32_t)(ar * ASTR + ak) * 4u;
    uint32_t sB0 = smem_u32(sm) + (uint32_t)(128 * ASTR + bk * BSTR + bn) * 4u;

    auto issue = [&](int kt) {
        const uint32_t so = (uint32_t)(kt & 3) * (STG_FLT * 4u);
        const float* ap = Ag + kt * 16;
        const float* bp = Bg + (size_t)(kt * 16) * N;
        cp16(sA0 + so,      ap);
        cp16(sA0 + so + 16, ap + 4);
        cp16(sB0 + so,      bp);
        cp16(sB0 + so + 16, bp + 4);
        cp_commit();
    };

    float acc[4][4][4];
    #pragma unroll
    for (int mi = 0; mi < 4; mi++)
        #pragma unroll
        for (int nj = 0; nj < 4; nj++)
            #pragma unroll
            for (int r = 0; r < 4; r++) acc[mi][nj][r] = 0.f;

    const int nk = K >> 4;

    issue(0); issue(1); issue(2);

    for (int kt = 0; kt < nk; ++kt) {
        if (kt + 2 < nk) cp_wait<2>(); else cp_wait<0>();   // tail fix
        __syncthreads();
        if (kt + 3 < nk) issue(kt + 3);

        const uint32_t* As32 = (const uint32_t*)(sm + (kt & 3) * STG_FLT);
        const uint32_t* Bs32 = As32 + 128 * ASTR;

        #pragma unroll
        for (int ks = 0; ks < 2; ++ks) {
            const int k0 = ks * 8;
            uint32_t a[4][4], b[4][2];
            #pragma unroll
            for (int mi = 0; mi < 4; mi++) {
                const int m0 = wm + mi * 16 + g;
                a[mi][0] = As32[(m0    ) * ASTR + k0 + q];
                a[mi][1] = As32[(m0 + 8) * ASTR + k0 + q];
                a[mi][2] = As32[(m0    ) * ASTR + k0 + q + 4];
                a[mi][3] = As32[(m0 + 8) * ASTR + k0 + q + 4];
            }
            #pragma unroll
            for (int nj = 0; nj < 4; nj++) {
                const int n0 = wn + nj * 8 + g;
                b[nj][0] = Bs32[(k0 + q    ) * BSTR + n0];
                b[nj][1] = Bs32[(k0 + q + 4) * BSTR + n0];
            }
            #pragma unroll
            for (int mi = 0; mi < 4; mi++)
                #pragma unroll
                for (int nj = 0; nj < 4; nj++)
                    mma_tf32(acc[mi][nj], a[mi][0], a[mi][1], a[mi][2], a[mi][3],
                             b[nj][0], b[nj][1]);
        }
    }

    // ---- epilogue ----
    #pragma unroll
    for (int nj = 0; nj < 4; nj++) {
        const int col = bx * 128 + wn + nj * 8 + 2 * q;
        const float2 bb = *(const float2*)&bias[col];
        #pragma unroll
        for (int mi = 0; mi < 4; mi++) {
            const int row0 = by * 128 + wm + mi * 16 + g;
            float2 o0, o1;
            o0.x = acc[mi][nj][0] + bb.x;
            o0.y = acc[mi][nj][1] + bb.y;
            o1.x = acc[mi][nj][2] + bb.x;
            o1.y = acc[mi][nj][3] + bb.y;
            if (ACT == 1) {
                o0.x = gelu_erf_f(o0.x); o0.y = gelu_erf_f(o0.y);
                o1.x = gelu_erf_f(o1.x); o1.y = gelu_erf_f(o1.y);
            }
            if (ROUND == 1) {
                o0.x = tf32r(o0.x); o0.y = tf32r(o0.y);
                o1.x = tf32r(o1.x); o1.y = tf32r(o1.y);
            }
            *(float2*)&C[(size_t)row0 * N + col]       = o0;
            *(float2*)&C[(size_t)(row0 + 8) * N + col] = o1;
        }
    }
}

// ---------------------------------------------------------------------------
// Fused attention: 32-row q-tiles, grid (S/32, H, B), 256 threads.
// smem: sc[32][516] + qs[32][68] + kv[64][68] = 92,160 bytes -> 2 CTAs/SM.
// Same per-element math as r9; emits tf32-rounded ctx.
// ---------------------------------------------------------------------------
#define SC_STRIDE 516
#define QK_STRIDE 68
#define ATTN_SMEM ((32 * SC_STRIDE + 32 * QK_STRIDE + 64 * QK_STRIDE) * 4)

__global__ __launch_bounds__(256) void attention_kernel(
    const float* __restrict__ Q, const float* __restrict__ K,
    const float* __restrict__ V, const int* __restrict__ mask,
    const float* __restrict__ adj, float* __restrict__ ctx)
{
    extern __shared__ float smem[];
    float* sc = smem;                        // 32 * 516
    float* qs = sc + 32 * SC_STRIDE;         // 32 * 68
    float* kv = qs + 32 * QK_STRIDE;         // 64 * 68

    const int t  = threadIdx.x;
    const int qt = blockIdx.x, h = blockIdx.y, b = blockIdx.z;
    const int qbase = b * S_ + qt * 32;

    // load Q tile (32x64), pre-scaled by 1/8
    #pragma unroll
    for (int i = 0; i < 2; i++) {
        int lin = t + i * 256;               // 0..511 over 32 rows x 16 f4
        int r = lin >> 4, c4 = (lin & 15) << 2;
        float4 qv = *(const float4*)&Q[(size_t)(qbase + r) * D_ + h * DK_ + c4];
        qv.x *= 0.125f; qv.y *= 0.125f; qv.z *= 0.125f; qv.w *= 0.125f;
        *(float4*)&qs[r * QK_STRIDE + c4] = qv;
    }

    const int qi  = t >> 3;          // 0..31
    const int kj0 = (t & 7) << 3;    // 0,8,..,56
    const int qg  = qt * 32 + qi;

    // ---- phase 1: scores ----
    for (int kt = 0; kt < 8; ++kt) {
        __syncthreads();   // protect kv reuse (and qs stores on kt==0)
        #pragma unroll
        for (int i = 0; i < 4; i++) {
            int lin = t + i * 256;           // 0..1023 over 64 rows x 16 f4
            int r = lin >> 4, c4 = (lin & 15) << 2;
            float4 kk = *(const float4*)&K[(size_t)(b * S_ + kt * 64 + r) * D_ + h * DK_ + c4];
            kv[(c4 + 0) * QK_STRIDE + r] = kk.x;   // transposed kv[d][kj]
            kv[(c4 + 1) * QK_STRIDE + r] = kk.y;
            kv[(c4 + 2) * QK_STRIDE + r] = kk.z;
            kv[(c4 + 3) * QK_STRIDE + r] = kk.w;
        }
        __syncthreads();

        float acc[8];
        #pragma unroll
        for (int j = 0; j < 8; j++) acc[j] = 0.f;

        #pragma unroll
        for (int d = 0; d < 64; ++d) {
            float qv = qs[qi * QK_STRIDE + d];
            const float4* kr = (const float4*)&kv[d * QK_STRIDE + kj0];
            float4 k0 = kr[0], k1 = kr[1];
            acc[0] += qv * k0.x; acc[1] += qv * k0.y; acc[2] += qv * k0.z; acc[3] += qv * k0.w;
            acc[4] += qv * k1.x; acc[5] += qv * k1.y; acc[6] += qv * k1.z; acc[7] += qv * k1.w;
        }

        const float* adjr = &adj[((size_t)(b * S_ + qg)) * S_ + kt * 64 + kj0];
        const int*   mr   = &mask[b * S_ + kt * 64 + kj0];
        float*       scr  = &sc[qi * SC_STRIDE + kt * 64 + kj0];
        #pragma unroll
        for (int j = 0; j < 8; j++)
            scr[j] = acc[j] + (float)mr[j] * -1e9f + adjr[j];
    }
    __syncthreads();

    // ---- phase 2: softmax (8 warps, 32 rows) ----
    {
        const int warp = t >> 5, lane = t & 31;
        for (int row = warp; row < 32; row += 8) {
            float* r = &sc[row * SC_STRIDE];
            float mx = -3.0e38f;
            #pragma unroll
            for (int i = 0; i < 16; i++) mx = fmaxf(mx, r[lane + 32 * i]);
            #pragma unroll
            for (int o = 16; o; o >>= 1) mx = fmaxf(mx, __shfl_xor_sync(0xffffffffu, mx, o));
            float e[16], sum = 0.f;
            #pragma unroll
            for (int i = 0; i < 16; i++) { e[i] = __expf(r[lane + 32 * i] - mx); sum += e[i]; }
            #pragma unroll
            for (int o = 16; o; o >>= 1) sum += __shfl_xor_sync(0xffffffffu, sum, o);
            const float inv = 1.0f / sum;
            #pragma unroll
            for (int i = 0; i < 16; i++) r[lane + 32 * i] = e[i] * inv;
        }
    }

    // ---- phase 3: ctx = P @ V ----
    const int dc0 = kj0;
    float acc[8];
    #pragma unroll
    for (int j = 0; j < 8; j++) acc[j] = 0.f;

    for (int kt = 0; kt < 8; ++kt) {
        __syncthreads();
        #pragma unroll
        for (int i = 0; i < 4; i++) {
            int lin = t + i * 256;
            int r = lin >> 4, c4 = (lin & 15) << 2;
            float4 vv = *(const float4*)&V[(size_t)(b * S_ + kt * 64 + r) * D_ + h * DK_ + c4];
            *(float4*)&kv[r * QK_STRIDE + c4] = vv;   // row-major kv[k][d]
        }
        __syncthreads();

        #pragma unroll
        for (int kk = 0; kk < 64; ++kk) {
            float p = sc[qi * SC_STRIDE + kt * 64 + kk];
            const float4* vr = (const float4*)&kv[kk * QK_STRIDE + dc0];
            float4 v0 = vr[0], v1 = vr[1];
            acc[0] += p * v0.x; acc[1] += p * v0.y; acc[2] += p * v0.z; acc[3] += p * v0.w;
            acc[4] += p * v1.x; acc[5] += p * v1.y; acc[6] += p * v1.z; acc[7] += p * v1.w;
        }
    }

    float* outp = &ctx[(size_t)(qbase + qi) * D_ + h * DK_ + dc0];
    float4 o0, o1;
    o0.x = tf32r(acc[0]); o0.y = tf32r(acc[1]); o0.z = tf32r(acc[2]); o0.w = tf32r(acc[3]);
    o1.x = tf32r(acc[4]); o1.y = tf32r(acc[5]); o1.z = tf32r(acc[6]); o1.w = tf32r(acc[7]);
    *(float4*)&outp[0] = o0;
    *(float4*)&outp[4] = o1;
}

// ---------------------------------------------------------------------------
// Residual + LayerNorm; optional tf32-rounded secondary output
// ---------------------------------------------------------------------------
__device__ __forceinline__ float blockReduceSum(float val, float* shared) {
    const int lane = threadIdx.x & 31, wid = threadIdx.x >> 5;
    #pragma unroll
    for (int o = 16; o; o >>= 1) val += __shfl_xor_sync(0xffffffffu, val, o);
    __syncthreads();
    if (lane == 0) shared[wid] = val;
    __syncthreads();
    float r = shared[0];
    #pragma unroll
    for (int w = 1; w < 8; w++) r += shared[w];
    return r;
}

template <int WR>
__global__ __launch_bounds__(256) void ln_residual_kernel(
    const float* __restrict__ A, const float* __restrict__ Bm,
    const float* __restrict__ gamma, const float* __restrict__ beta,
    float* __restrict__ out, float* __restrict__ outR)
{
    __shared__ float red[8];
    const int row = blockIdx.x;
    const int tid = threadIdx.x;
    const size_t base = (size_t)row * D_;

    float v[4];
    float s = 0.f;
    #pragma unroll
    for (int i = 0; i < 4; i++) {
        int c = tid + 256 * i;
        v[i] = A[base + c] + Bm[base + c];
        s += v[i];
    }
    s = blockReduceSum(s, red);
    const float mean = s * (1.0f / (float)D_);

    float s2 = 0.f;
    #pragma unroll
    for (int i = 0; i < 4; i++) { float d = v[i] - mean; s2 += d * d; }
    s2 = blockReduceSum(s2, red);

    const float stdv = sqrtf(s2 * (1.0f / (float)(D_ - 1)));   // ddof=1
    const float inv  = 1.0f / (stdv + 1e-6f);                  // /(std+eps)

    #pragma unroll
    for (int i = 0; i < 4; i++) {
        int c = tid + 256 * i;
        float o = gamma[c] * (v[i] - mean) * inv + beta[c];
        out[base + c] = o;
        if (WR) outR[base + c] = tf32r(o);
    }
}

// ---------------------------------------------------------------------------
// launch
// ---------------------------------------------------------------------------
extern "C" void kernel_launch(void* const* d_in, const int* in_sizes, int n_in,
                              void* d_out, int out_size)
{
    const float* x    = (const float*)d_in[0];
    const int*   mask = (const int*)  d_in[1];
    const float* adj  = (const float*)d_in[2];
    const float* Wq = (const float*)d_in[4];  const float* bq = (const float*)d_in[5];
    const float* Wk = (const float*)d_in[6];  const float* bk = (const float*)d_in[7];
    const float* Wv = (const float*)d_in[8];  const float* bv = (const float*)d_in[9];
    const float* Wo = (const float*)d_in[10]; const float* bo = (const float*)d_in[11];
    const float* W1 = (const float*)d_in[12]; const float* b1 = (const float*)d_in[13];
    const float* W2 = (const float*)d_in[14]; const float* b2 = (const float*)d_in[15];
    const float* gamma = (const float*)d_in[16];
    const float* beta  = (const float*)d_in[17];
    float* out = (float*)d_out;

    float *q, *k, *v, *ctx, *attn, *out1, *out1r, *ffn, *hbuf;
    float *xr, *wqr, *wkr, *wvr, *wor, *w1r, *w2r;
    cudaGetSymbolAddress((void**)&q,     g_q);
    cudaGetSymbolAddress((void**)&k,     g_k);
    cudaGetSymbolAddress((void**)&v,     g_v);
    cudaGetSymbolAddress((void**)&ctx,   g_ctx);
    cudaGetSymbolAddress((void**)&attn,  g_attn);
    cudaGetSymbolAddress((void**)&out1,  g_out1);
    cudaGetSymbolAddress((void**)&out1r, g_out1r);
    cudaGetSymbolAddress((void**)&ffn,   g_ffn);
    cudaGetSymbolAddress((void**)&hbuf,  g_h);
    cudaGetSymbolAddress((void**)&xr,    g_xr);
    cudaGetSymbolAddress((void**)&wqr,   g_wqr);
    cudaGetSymbolAddress((void**)&wkr,   g_wkr);
    cudaGetSymbolAddress((void**)&wvr,   g_wvr);
    cudaGetSymbolAddress((void**)&wor,   g_wor);
    cudaGetSymbolAddress((void**)&w1r,   g_w1r);
    cudaGetSymbolAddress((void**)&w2r,   g_w2r);

    cudaFuncSetAttribute(tf32_gemm<0,0>,
                         cudaFuncAttributeMaxDynamicSharedMemorySize, GEMM_SMEM);
    cudaFuncSetAttribute(tf32_gemm<1,1>,
                         cudaFuncAttributeMaxDynamicSharedMemorySize, GEMM_SMEM);
    cudaFuncSetAttribute(attention_kernel,
                         cudaFuncAttributeMaxDynamicSharedMemorySize, ATTN_SMEM);

    // ---- preprocessing: rna-round GEMM operands (batched) ----
    rnd_kernel<<<(M_ * D_ / 4 + 255) / 256, 256>>>(x, xr, M_ * D_ / 4);
    rnd4_kernel<<<(4 * D_ * D_ / 4) / 256, 256>>>(Wq, Wk, Wv, Wo,
                                                  wqr, wkr, wvr, wor);
    rnd_kernel<<<(D_ * F_ / 4 + 255) / 256, 256>>>(W1, w1r, D_ * F_ / 4);
    rnd_kernel<<<(F_ * D_ / 4 + 255) / 256, 256>>>(W2, w2r, F_ * D_ / 4);

    dim3 gD(D_ / 128, M_ / 128);   // (8, 128)
    dim3 gF(F_ / 128, M_ / 128);   // (32, 128)

    // QKV projections (outputs exact fp32 -> attention)
    tf32_gemm<0,0><<<gD, 256, GEMM_SMEM>>>(xr, wqr, bq, q, D_, D_);
    tf32_gemm<0,0><<<gD, 256, GEMM_SMEM>>>(xr, wkr, bk, k, D_, D_);
    tf32_gemm<0,0><<<gD, 256, GEMM_SMEM>>>(xr, wvr, bv, v, D_, D_);

    // attention (fp32 compute; emits rounded ctx), 2 CTAs/SM
    dim3 gA(S_ / 32, H_, B_);
    attention_kernel<<<gA, 256, ATTN_SMEM>>>(q, k, v, mask, adj, ctx);

    // output projection
    tf32_gemm<0,0><<<gD, 256, GEMM_SMEM>>>(ctx, wor, bo, attn, D_, D_);

    // LN1: out1 = LN(x + attn); exact + rounded
    ln_residual_kernel<1><<<M_, 256>>>(x, attn, gamma, beta, out1, out1r);

    // FFN
    tf32_gemm<1,1><<<gF, 256, GEMM_SMEM>>>(out1r, w1r, b1, hbuf, F_, D_);
    tf32_gemm<0,0><<<gD, 256, GEMM_SMEM>>>(hbuf, w2r, b2, ffn, D_, F_);

    // LN2: out = LN(out1 + ffn)
    ln_residual_kernel<0><<<M_, 256>>>(out1, ffn, gamma, beta, out, (float*)0);
}